// round 10
// baseline (speedup 1.0000x reference)
#include <cuda_runtime.h>
#include <math.h>

#define BROWS 16384
#define DDIM  256
#define TTRIP 262144
#define MARGIN 0.1f
#define EPSN   1e-6f

// Scratch (no allocations allowed in kernel_launch)
__device__ unsigned char g_predq[BROWS * DDIM];  // normalized int8 rows, 4 MB
__device__ float         g_scale[BROWS];         // per-row dequant step (maxabs/127)
__device__ double        g_accum;

// ---------------------------------------------------------------------------
// Kernel A: per-row inverse norm + normalize + per-row-scale int8 quant.
// One warp per FOUR rows: 8 front-batched LDG.128 per thread (MLP=8) to fill
// the DRAM pipe; 4 interleaved shuffle-reduction chains amortize SHFL latency.
// Also zeroes the accumulator (graph replays re-run this).
// ---------------------------------------------------------------------------
__global__ void __launch_bounds__(256) normconv_kernel(const float* __restrict__ pred) {
    if (blockIdx.x == 0 && threadIdx.x == 0) g_accum = 0.0;

    int gw   = (blockIdx.x * blockDim.x + threadIdx.x) >> 5;  // warp id
    int lane = threadIdx.x & 31;
    int rbase = gw * 4;

    // front-batch all 8 row-loads (2 per row x 4 rows)
    float4 v[4][2];
    #pragma unroll
    for (int r = 0; r < 4; r++) {
        const float4* row = reinterpret_cast<const float4*>(pred + (size_t)(rbase + r) * DDIM);
        v[r][0] = row[lane * 2 + 0];
        v[r][1] = row[lane * 2 + 1];
    }

    float ss[4];
    #pragma unroll
    for (int r = 0; r < 4; r++) {
        float4 a = v[r][0], b = v[r][1];
        ss[r] = a.x*a.x + a.y*a.y + a.z*a.z + a.w*a.w
              + b.x*b.x + b.y*b.y + b.z*b.z + b.w*b.w;
    }

    #pragma unroll
    for (int o = 16; o > 0; o >>= 1) {
        #pragma unroll
        for (int r = 0; r < 4; r++)
            ss[r] += __shfl_xor_sync(0xFFFFFFFFu, ss[r], o);
    }

    #pragma unroll
    for (int r = 0; r < 4; r++) {
        float inv = 1.0f / fmaxf(sqrtf(ss[r]), EPSN);
        float4 a = v[r][0], b = v[r][1];
        float x0 = a.x*inv, x1 = a.y*inv, x2 = a.z*inv, x3 = a.w*inv;
        float x4 = b.x*inv, x5 = b.y*inv, x6 = b.z*inv, x7 = b.w*inv;

        float ma = fmaxf(fmaxf(fmaxf(fabsf(x0), fabsf(x1)), fmaxf(fabsf(x2), fabsf(x3))),
                         fmaxf(fmaxf(fabsf(x4), fabsf(x5)), fmaxf(fabsf(x6), fabsf(x7))));
        float maxabs = fmaxf(__uint_as_float(
            __reduce_max_sync(0xFFFFFFFFu, __float_as_uint(ma))), 1e-20f);

        float qs = 127.0f / maxabs;
        int q0 = __float2int_rn(x0*qs), q1 = __float2int_rn(x1*qs);
        int q2 = __float2int_rn(x2*qs), q3 = __float2int_rn(x3*qs);
        int q4 = __float2int_rn(x4*qs), q5 = __float2int_rn(x5*qs);
        int q6 = __float2int_rn(x6*qs), q7 = __float2int_rn(x7*qs);

        uint2 pk;
        pk.x = (unsigned)(q0&0xFF) | ((unsigned)(q1&0xFF)<<8) |
               ((unsigned)(q2&0xFF)<<16) | ((unsigned)(q3&0xFF)<<24);
        pk.y = (unsigned)(q4&0xFF) | ((unsigned)(q5&0xFF)<<8) |
               ((unsigned)(q6&0xFF)<<16) | ((unsigned)(q7&0xFF)<<24);

        reinterpret_cast<uint2*>(g_predq + (size_t)(rbase + r) * DDIM)[lane] = pk;
        if (lane == r) g_scale[rbase + r] = maxabs * (1.0f / 127.0f);
    }
}

// ---------------------------------------------------------------------------
// Kernel B: half-warp-per-triplet (at the chip LTS cap — do not touch).
// lanes 0-15 -> triplet 2i, lanes 16-31 -> triplet 2i+1; uint4 per lane.
// Segmented __reduce_add_sync per half. One double atomicAdd per block.
// ---------------------------------------------------------------------------
#define ITERS 16   // triplets per warp = 2*ITERS = 32

__global__ void __launch_bounds__(256) triplet_kernel(
    const int* __restrict__ aidx,
    const int* __restrict__ pidx,
    const int* __restrict__ nidx)
{
    int gw     = (blockIdx.x * blockDim.x + threadIdx.x) >> 5;  // global warp
    int lane   = threadIdx.x & 31;
    int half   = lane >> 4;          // 0 or 1
    int lane16 = lane & 15;
    int wib    = threadIdx.x >> 5;

    unsigned hmask = half ? 0xFFFF0000u : 0x0000FFFFu;

    __shared__ float part[16];

    int base = gw * (2 * ITERS);
    float acc = 0.0f;

    #pragma unroll 2
    for (int i = 0; i < ITERS; i++) {
        int t = base + 2 * i + half;
        int a = aidx[t];
        int p = pidx[t];
        int n = nidx[t];

        const uint4* ra = reinterpret_cast<const uint4*>(g_predq + (size_t)a * DDIM);
        const uint4* rp = reinterpret_cast<const uint4*>(g_predq + (size_t)p * DDIM);
        const uint4* rn = reinterpret_cast<const uint4*>(g_predq + (size_t)n * DDIM);

        uint4 av = ra[lane16];
        uint4 pv = rp[lane16];
        uint4 nv = rn[lane16];

        int dap = __dp4a((int)av.x, (int)pv.x, 0);
        dap     = __dp4a((int)av.y, (int)pv.y, dap);
        dap     = __dp4a((int)av.z, (int)pv.z, dap);
        dap     = __dp4a((int)av.w, (int)pv.w, dap);
        int dan = __dp4a((int)av.x, (int)nv.x, 0);
        dan     = __dp4a((int)av.y, (int)nv.y, dan);
        dan     = __dp4a((int)av.z, (int)nv.z, dan);
        dan     = __dp4a((int)av.w, (int)nv.w, dan);

        dap = __reduce_add_sync(hmask, dap);
        dan = __reduce_add_sync(hmask, dan);

        float sa = g_scale[a];
        float sp = g_scale[p];
        float sn = g_scale[n];
        float v = (float)dap * (sa * sp) - (float)dan * (sa * sn) + MARGIN;
        acc += fmaxf(v, 0.0f);
    }

    if (lane16 == 0) part[wib * 2 + half] = acc;
    __syncthreads();

    if (threadIdx.x == 0) {
        float s = 0.0f;
        #pragma unroll
        for (int i = 0; i < 16; i++) s += part[i];
        atomicAdd(&g_accum, (double)s);
    }
}

// ---------------------------------------------------------------------------
// Kernel C: finalize the mean
// ---------------------------------------------------------------------------
__global__ void finalize_kernel(float* __restrict__ out) {
    out[0] = (float)(g_accum / (double)TTRIP);
}

extern "C" void kernel_launch(void* const* d_in, const int* in_sizes, int n_in,
                              void* d_out, int out_size) {
    const float* pred = (const float*)d_in[0];
    const int*   ai   = (const int*)d_in[1];
    const int*   pi   = (const int*)d_in[2];
    const int*   ni   = (const int*)d_in[3];
    float* out = (float*)d_out;

    normconv_kernel<<<BROWS / 32, 256>>>(pred);                      // 512 blocks, 4 rows/warp
    triplet_kernel<<<TTRIP / (8 * 2 * ITERS), 256>>>(ai, pi, ni);    // 1024 blocks, 32 trip/warp
    finalize_kernel<<<1, 1>>>(out);
}